// round 11
// baseline (speedup 1.0000x reference)
#include <cuda_runtime.h>
#include <cuda_bf16.h>
#include <cstdint>

// ===========================================================================
// Problem constants
// ===========================================================================
#define B_SZ 32768
#define D_SZ 256
#define K_SZ 1024

#define NTHREADS 512       // 16 warps
#define BK 32              // d-chunk per B pipeline stage

// --- SMEM layout (bytes) for K3 ---
// B tiles: [buf(2)][limb(2)] each 128 codes x 32 d bf16, row stride 80B
#define BT_STRIDE 80
#define BT_SZ     10240          // 128*80
#define BUFB      20480          // 2 limbs
#define OFF_B     0              // 2 bufs -> 40960
// A tiles: [limb(2)] 128 rows x 256 d bf16, row stride 528B (512 + 16 pad)
#define AT_STRIDE 528
#define A_LIMB    67584          // 128*528
#define OFF_A     40960          // 2 limbs -> ends 176128
#define OFF_INVN  176128         // 256 floats -> 177152
#define OFF_CS1   177152         // float [128][16] -> 185344
#define OFF_CI1   185344         // int   [128][16] -> 193536
#define OFF_CS2   193536         // float [128][16] -> 201728
#define SMEM_K3   201728

// ===========================================================================
// Device scratch (allocation-free rule: __device__ globals)
// ===========================================================================
__device__ float g_inv_norms[K_SZ];
__device__ __align__(16) __nv_bfloat16 g_Ehi[B_SZ * D_SZ];
__device__ __align__(16) __nv_bfloat16 g_Elo[B_SZ * D_SZ];
__device__ __align__(16) __nv_bfloat16 g_Chi[K_SZ * D_SZ];
__device__ __align__(16) __nv_bfloat16 g_Clo[K_SZ * D_SZ];
// per (quarter, row) top-2 approx results
__device__ float g_ts1[4 * B_SZ];
__device__ int   g_ti1[4 * B_SZ];
__device__ float g_ts2[4 * B_SZ];

// ===========================================================================
// PTX helpers (plain sm_103-safe: mma.sync / ldmatrix / cp.async only)
// ===========================================================================
__device__ __forceinline__ uint32_t smem_u32(const void* p) {
    uint32_t a;
    asm("{ .reg .u64 t; cvta.to.shared.u64 t, %1; cvt.u32.u64 %0, t; }" : "=r"(a) : "l"(p));
    return a;
}
__device__ __forceinline__ void ldsm_x4(uint32_t r[4], uint32_t addr) {
    asm volatile("ldmatrix.sync.aligned.m8n8.x4.shared.b16 {%0,%1,%2,%3}, [%4];"
                 : "=r"(r[0]), "=r"(r[1]), "=r"(r[2]), "=r"(r[3]) : "r"(addr));
}
__device__ __forceinline__ void mma_bf16(float d[4], const uint32_t a[4], const uint32_t* b) {
    asm volatile(
        "mma.sync.aligned.m16n8k16.row.col.f32.bf16.bf16.f32 "
        "{%0,%1,%2,%3}, {%4,%5,%6,%7}, {%8,%9}, {%0,%1,%2,%3};"
        : "+f"(d[0]), "+f"(d[1]), "+f"(d[2]), "+f"(d[3])
        : "r"(a[0]), "r"(a[1]), "r"(a[2]), "r"(a[3]), "r"(b[0]), "r"(b[1]));
}
#define CP_ASYNC16(dst, src) \
    asm volatile("cp.async.cg.shared.global [%0], [%1], 16;" :: "r"(dst), "l"(src) : "memory")
#define CP_COMMIT() asm volatile("cp.async.commit_group;" ::: "memory")
#define CP_WAIT(N)  asm volatile("cp.async.wait_group %0;" :: "n"(N) : "memory")

__device__ __forceinline__ float warp_allsum(float v) {
#pragma unroll
    for (int o = 16; o > 0; o >>= 1) v += __shfl_xor_sync(0xffffffffu, v, o);
    return v;
}

// ===========================================================================
// K1: inv_norms[k] = 1 / ||C[k]||^2   (one warp per code)
// ===========================================================================
__global__ void vq_norms_kernel(const float* __restrict__ C) {
    int k = blockIdx.x;
    int lane = threadIdx.x;
    const float4* row = reinterpret_cast<const float4*>(C + (size_t)k * D_SZ);
    float s = 0.f;
#pragma unroll
    for (int i = 0; i < 2; i++) {
        float4 v = row[lane + 32 * i];
        s += v.x * v.x + v.y * v.y + v.z * v.z + v.w * v.w;
    }
    s = warp_allsum(s);
    if (lane == 0) g_inv_norms[k] = 1.0f / s;
}

// ===========================================================================
// K2: 2-limb bf16 split (a ~= hi + lo, ~17 mantissa bits)
// ===========================================================================
__global__ void vq_split_kernel(const float* __restrict__ src, int n8, int isC) {
    int i = blockIdx.x * blockDim.x + threadIdx.x;
    if (i >= n8) return;
    __nv_bfloat16* dh = isC ? g_Chi : g_Ehi;
    __nv_bfloat16* dl = isC ? g_Clo : g_Elo;
    const float4* p = reinterpret_cast<const float4*>(src) + (size_t)i * 2;
    float4 f0 = p[0], f1 = p[1];
    float v[8] = {f0.x, f0.y, f0.z, f0.w, f1.x, f1.y, f1.z, f1.w};
    union U8 { __nv_bfloat16 h[8]; uint4 u; } uh, ul;
#pragma unroll
    for (int j = 0; j < 8; j++) {
        float a = v[j];
        __nv_bfloat16 bh = __float2bfloat16_rn(a);
        float r = a - __bfloat162float(bh);
        uh.h[j] = bh;
        ul.h[j] = __float2bfloat16_rn(r);
    }
    *reinterpret_cast<uint4*>(dh + (size_t)i * 8) = uh.u;
    *reinterpret_cast<uint4*>(dl + (size_t)i * 8) = ul.u;
}

// ===========================================================================
// K3: 3-term split-bf16 mma.sync GEMM + per-row approx top-2
// grid = 1024: blockIdx = rb*4 + q. CTA: 128 rows x 256 codes, 512 threads.
// A (both limbs, full D) resident in SMEM; B double-buffered in BK=32 chunks.
// ===========================================================================
__global__ __launch_bounds__(NTHREADS, 1) void vq_gemm_kernel() {
    extern __shared__ char smem[];
    const uint32_t sb = smem_u32(smem);
    const int tid = threadIdx.x;
    const int lane = tid & 31;
    const int wid = tid >> 5;      // 0..15
    const int wm = wid & 3;        // M group: rows wm*32..+32
    const int wn = wid >> 2;       // N group: codes wn*32..+32 (within 128-pass)
    const int rb = blockIdx.x >> 2;
    const int q  = blockIdx.x & 3;
    const int rowA0 = rb * 128;

    float* s_invn = reinterpret_cast<float*>(smem + OFF_INVN);
    float* c_s1 = reinterpret_cast<float*>(smem + OFF_CS1);
    int*   c_i1 = reinterpret_cast<int*>(smem + OFF_CI1);
    float* c_s2 = reinterpret_cast<float*>(smem + OFF_CS2);

    if (tid < 256) s_invn[tid] = g_inv_norms[q * 256 + tid];

    // --- A prologue: load both limbs of this row block, full D (132 KB) ---
#pragma unroll
    for (int j = 0; j < 16; j++) {
        int id = tid + NTHREADS * j;          // 0..8191
        int limb = id >> 12;
        int w = id & 4095;
        int r = w >> 5;                        // 0..127
        int c = w & 31;                        // 16B column (32 per 512B row)
        const __nv_bfloat16* base = limb ? g_Elo : g_Ehi;
        CP_ASYNC16(sb + OFF_A + limb * A_LIMB + r * AT_STRIDE + c * 16,
                   base + (size_t)(rowA0 + r) * D_SZ + c * 8);
    }
    CP_COMMIT();

    // per-thread top-2 state for 4 owned rows (mt*2 + half)
    float st_s1[4], st_s2[4];
    int   st_i1[4];
#pragma unroll
    for (int i = 0; i < 4; i++) { st_s1[i] = -1.f; st_s2[i] = -1.f; st_i1[i] = 0; }

    // B chunk loader: 2 x 16B cp.async per thread
    auto loadB = [&](int buf, int kk, int codeB0) {
#pragma unroll
        for (int j = 0; j < 2; j++) {
            int id = tid + NTHREADS * j;       // 0..1023
            int limb = id >> 9;
            int w = id & 511;
            int r = w >> 2;                    // 0..127
            int c = w & 3;                     // 16B column
            const __nv_bfloat16* base = limb ? g_Clo : g_Chi;
            CP_ASYNC16(sb + OFF_B + buf * BUFB + limb * BT_SZ + r * BT_STRIDE + c * 16,
                       base + (size_t)(codeB0 + r) * D_SZ + kk + c * 8);
        }
        CP_COMMIT();
    };

    const int mi = lane >> 3;
    const int arow_off = ((mi & 1) * 8 + (lane & 7)) * AT_STRIDE;
    const int brow_off = ((mi >> 1) * 8 + (lane & 7)) * BT_STRIDE;

    for (int p = 0; p < 2; p++) {
        const int codeB0 = q * 256 + p * 128;
        float d[2][4][4];
#pragma unroll
        for (int mt = 0; mt < 2; mt++)
#pragma unroll
            for (int nt = 0; nt < 4; nt++)
#pragma unroll
                for (int e = 0; e < 4; e++) d[mt][nt][e] = 0.f;

        loadB(0, 0, codeB0);
        for (int kc = 0; kc < 8; kc++) {
            const int buf = kc & 1;
            if (kc < 7) { loadB(buf ^ 1, (kc + 1) * BK, codeB0); CP_WAIT(1); }
            else        { CP_WAIT(0); }
            __syncthreads();

#pragma unroll
            for (int ks2 = 0; ks2 < 2; ks2++) {
                const int d0 = kc * BK + ks2 * 16;   // absolute d for A
                const int ksl = ks2 * 16;            // local d within B chunk
                // A fragments: [limb][mt]
                uint32_t afr[2][2][4];
#pragma unroll
                for (int lb = 0; lb < 2; lb++)
#pragma unroll
                    for (int mt = 0; mt < 2; mt++) {
                        uint32_t ad = sb + OFF_A + lb * A_LIMB
                                    + (wm * 32 + mt * 16) * AT_STRIDE + arow_off
                                    + (d0 + (mi >> 1) * 8) * 2;
                        ldsm_x4(afr[lb][mt], ad);
                    }
                // B fragments per 16-code group, then MMAs
#pragma unroll
                for (int np = 0; np < 2; np++) {
                    uint32_t bh[4], bl[4];
                    uint32_t bd0 = sb + OFF_B + buf * BUFB
                                 + (wn * 32 + np * 16) * BT_STRIDE + brow_off
                                 + (ksl + (mi & 1) * 8) * 2;
                    ldsm_x4(bh, bd0);
                    ldsm_x4(bl, bd0 + BT_SZ);
#pragma unroll
                    for (int jj = 0; jj < 2; jj++) {
                        int nt = np * 2 + jj;
#pragma unroll
                        for (int mt = 0; mt < 2; mt++) {
                            mma_bf16(d[mt][nt], afr[0][mt], bh + jj * 2);  // hi*hi
                            mma_bf16(d[mt][nt], afr[0][mt], bl + jj * 2);  // hi*lo
                            mma_bf16(d[mt][nt], afr[1][mt], bh + jj * 2);  // lo*hi
                        }
                    }
                }
            }
            __syncthreads();
        }

        // epilogue: fold this pass's 128 codes into per-row top-2
#pragma unroll
        for (int mt = 0; mt < 2; mt++)
#pragma unroll
            for (int nt = 0; nt < 4; nt++) {
                int cb = wn * 32 + nt * 8 + (lane & 3) * 2;   // 0..127
                int cl = p * 128 + cb;
                float in0 = s_invn[cl], in1 = s_invn[cl + 1];
                int gc = q * 256 + cl;
#pragma unroll
                for (int half = 0; half < 2; half++) {
                    int si = mt * 2 + half;
                    float e0 = d[mt][nt][half * 2 + 0];
                    float e1 = d[mt][nt][half * 2 + 1];
                    float sc0 = e0 * e0 * in0;
                    if (sc0 > st_s1[si]) { st_s2[si] = st_s1[si]; st_s1[si] = sc0; st_i1[si] = gc; }
                    else if (sc0 > st_s2[si]) st_s2[si] = sc0;
                    float sc1 = e1 * e1 * in1;
                    if (sc1 > st_s1[si]) { st_s2[si] = st_s1[si]; st_s1[si] = sc1; st_i1[si] = gc + 1; }
                    else if (sc1 > st_s2[si]) st_s2[si] = sc1;
                }
            }
    }

    // cross-thread merge: 16 candidates per row (4 wn groups x 4 lane cols)
#pragma unroll
    for (int mt = 0; mt < 2; mt++)
#pragma unroll
        for (int half = 0; half < 2; half++) {
            int r = wm * 32 + mt * 16 + half * 8 + (lane >> 2);
            int slot = wn * 4 + (lane & 3);
            int si = mt * 2 + half;
            c_s1[r * 16 + slot] = st_s1[si];
            c_i1[r * 16 + slot] = st_i1[si];
            c_s2[r * 16 + slot] = st_s2[si];
        }
    __syncthreads();
    if (tid < 128) {
        float S1 = -1.f, S2 = -1.f; int I1 = 0;
#pragma unroll
        for (int s = 0; s < 16; s++) {
            float a1 = c_s1[tid * 16 + s];
            int   ai = c_i1[tid * 16 + s];
            float a2 = c_s2[tid * 16 + s];
            if (a1 > S1) { S2 = (S1 > a2) ? S1 : a2; I1 = ai; S1 = a1; }
            else if (a1 > S2) S2 = a1;
        }
        int o = q * B_SZ + rowA0 + tid;
        g_ts1[o] = S1; g_ti1[o] = I1; g_ts2[o] = S2;
    }
}

// ===========================================================================
// K4: finalize — certify winner or exact fp32 rescan (lane-parallel, fast);
// exact alpha; write z, idx. One warp per row, 8 warps per CTA.
// ===========================================================================
__global__ __launch_bounds__(256) void vq_final_kernel(
    const float* __restrict__ E, const float* __restrict__ C,
    float* __restrict__ z_out, float* __restrict__ idx_out, int write_idx)
{
    __shared__ float se[8][256];   // per-warp e row cache
    int warp = threadIdx.x >> 5;
    int lane = threadIdx.x & 31;
    int row = blockIdx.x * 8 + warp;
    const float4* E4 = reinterpret_cast<const float4*>(E);
    const float4* C4 = reinterpret_cast<const float4*>(C);

    float4 ev0 = E4[(size_t)row * 64 + lane * 2];
    float4 ev1 = E4[(size_t)row * 64 + lane * 2 + 1];
    *reinterpret_cast<float4*>(&se[warp][lane * 8])     = ev0;
    *reinterpret_cast<float4*>(&se[warp][lane * 8 + 4]) = ev1;
    float en2 = warp_allsum(ev0.x * ev0.x + ev0.y * ev0.y + ev0.z * ev0.z + ev0.w * ev0.w +
                            ev1.x * ev1.x + ev1.y * ev1.y + ev1.z * ev1.z + ev1.w * ev1.w);
    __syncwarp();

    // merge 4 quarter top-2 triples
    float S1 = -1.f, S2 = -1.f; int I1 = 0;
#pragma unroll
    for (int qq = 0; qq < 4; qq++) {
        float a1 = g_ts1[qq * B_SZ + row];
        int   ai = g_ti1[qq * B_SZ + row];
        float a2 = g_ts2[qq * B_SZ + row];
        if (a1 > S1) { S2 = (S1 > a2) ? S1 : a2; I1 = ai; S1 = a1; }
        else if (a1 > S2) S2 = a1;
    }

    float eps = en2 * (1.0f / 8192.0f);   // 2^-13 * ||e||^2 (proven threshold)
    int kbest = I1;
    if (!(S1 - S2 > eps)) {
        // exact fp32 rescan, lane-parallel: lane handles codes lane, lane+32, ...
        const float* e = se[warp];
        float best = -1.f; int bi = 0;
        for (int j = 0; j < 32; j++) {
            int k = lane + 32 * j;            // ascending per lane
            float dot = 0.f;
#pragma unroll 16
            for (int d4 = 0; d4 < 64; d4++) {
                float4 cv = __ldg(&C4[(size_t)k * 64 + d4]);
                const float4 eev = *reinterpret_cast<const float4*>(&e[d4 * 4]);
                dot = fmaf(eev.x, cv.x, dot);
                dot = fmaf(eev.y, cv.y, dot);
                dot = fmaf(eev.z, cv.z, dot);
                dot = fmaf(eev.w, cv.w, dot);
            }
            float sc = dot * dot * g_inv_norms[k];
            if (sc > best) { best = sc; bi = k; }   // strict >: lowest k per lane
        }
        // cross-lane argmax with min-index tie-break
#pragma unroll
        for (int o = 16; o > 0; o >>= 1) {
            float ob = __shfl_xor_sync(0xffffffffu, best, o);
            int   oi = __shfl_xor_sync(0xffffffffu, bi, o);
            if (ob > best || (ob == best && oi < bi)) { best = ob; bi = oi; }
        }
        kbest = bi;
    }

    // exact dot for winner -> alpha, z
    float4 cv0 = __ldg(&C4[(size_t)kbest * 64 + lane * 2]);
    float4 cv1 = __ldg(&C4[(size_t)kbest * 64 + lane * 2 + 1]);
    float pp = ev0.x * cv0.x + ev0.y * cv0.y + ev0.z * cv0.z + ev0.w * cv0.w +
               ev1.x * cv1.x + ev1.y * cv1.y + ev1.z * cv1.z + ev1.w * cv1.w;
    float dot = warp_allsum(pp);
    float alpha = dot * g_inv_norms[kbest];
    float4* Z4 = reinterpret_cast<float4*>(z_out);
    Z4[(size_t)row * 64 + lane * 2] =
        make_float4(alpha * cv0.x, alpha * cv0.y, alpha * cv0.z, alpha * cv0.w);
    Z4[(size_t)row * 64 + lane * 2 + 1] =
        make_float4(alpha * cv1.x, alpha * cv1.y, alpha * cv1.z, alpha * cv1.w);
    if (lane == 0 && write_idx) idx_out[row] = (float)kbest;
}

// ===========================================================================
extern "C" void kernel_launch(void* const* d_in, const int* in_sizes, int n_in,
                              void* d_out, int out_size) {
    const float* E = (const float*)d_in[0];
    const float* C = (const float*)d_in[1];
    float* z = (float*)d_out;
    float* idx = z + (size_t)B_SZ * D_SZ;
    int write_idx = (out_size >= B_SZ * D_SZ + B_SZ) ? 1 : 0;

    cudaFuncSetAttribute(vq_gemm_kernel,
                         cudaFuncAttributeMaxDynamicSharedMemorySize, SMEM_K3);

    vq_norms_kernel<<<K_SZ, 32>>>(C);
    vq_split_kernel<<<(B_SZ * D_SZ / 8 + 255) / 256, 256>>>(E, B_SZ * D_SZ / 8, 0);
    vq_split_kernel<<<(K_SZ * D_SZ / 8 + 255) / 256, 256>>>(C, K_SZ * D_SZ / 8, 1);
    vq_gemm_kernel<<<1024, NTHREADS, SMEM_K3>>>();
    vq_final_kernel<<<B_SZ / 8, 256>>>(E, C, z, idx, write_idx);
}

// round 12
// speedup vs baseline: 1.8059x; 1.8059x over previous
#include <cuda_runtime.h>
#include <cuda_bf16.h>
#include <cstdint>

// ===========================================================================
// Problem constants
// ===========================================================================
#define B_SZ 32768
#define D_SZ 256
#define K_SZ 1024

#define NTHREADS 512       // 16 warps
#define BK 32              // d-chunk per B pipeline stage
#define FB_CTAS 512        // fallback kernel grid

// --- SMEM layout (bytes) for K3 ---
// B tiles: [buf(3)][limb(2)] each 128 codes x 32 d bf16, row stride 80B
#define BT_STRIDE 80
#define BT_SZ     10240          // 128*80
#define BUFB      20480          // 2 limbs
#define OFF_B     0              // 3 bufs -> 61440
// A tiles: [limb(2)] 128 rows x 256 d bf16, row stride 528B (512 + 16 pad)
#define AT_STRIDE 528
#define A_LIMB    67584          // 128*528
#define OFF_A     61440          // 2 limbs -> ends 196608
#define OFF_INVN  196608         // 256 floats -> 197632
#define OFF_CS1   197632         // float [128][16] -> 205824
#define OFF_CI1   205824         // int   [128][16] -> 214016
#define OFF_CS2   214016         // float [128][16] -> 222208
#define SMEM_K3   222208

// ===========================================================================
// Device scratch (allocation-free rule: __device__ globals)
// ===========================================================================
__device__ float g_inv_norms[K_SZ];
__device__ __align__(16) __nv_bfloat16 g_Ehi[B_SZ * D_SZ];
__device__ __align__(16) __nv_bfloat16 g_Elo[B_SZ * D_SZ];
__device__ __align__(16) __nv_bfloat16 g_Chi[K_SZ * D_SZ];
__device__ __align__(16) __nv_bfloat16 g_Clo[K_SZ * D_SZ];
// per (quarter, row) top-2 approx results
__device__ float g_ts1[4 * B_SZ];
__device__ int   g_ti1[4 * B_SZ];
__device__ float g_ts2[4 * B_SZ];
// fallback compaction
__device__ int g_fb_count;
__device__ int g_fb_rows[B_SZ];

// ===========================================================================
// PTX helpers (plain sm_103-safe: mma.sync / ldmatrix / cp.async only)
// ===========================================================================
__device__ __forceinline__ uint32_t smem_u32(const void* p) {
    uint32_t a;
    asm("{ .reg .u64 t; cvta.to.shared.u64 t, %1; cvt.u32.u64 %0, t; }" : "=r"(a) : "l"(p));
    return a;
}
__device__ __forceinline__ void ldsm_x4(uint32_t r[4], uint32_t addr) {
    asm volatile("ldmatrix.sync.aligned.m8n8.x4.shared.b16 {%0,%1,%2,%3}, [%4];"
                 : "=r"(r[0]), "=r"(r[1]), "=r"(r[2]), "=r"(r[3]) : "r"(addr));
}
__device__ __forceinline__ void mma_bf16(float d[4], const uint32_t a[4], const uint32_t* b) {
    asm volatile(
        "mma.sync.aligned.m16n8k16.row.col.f32.bf16.bf16.f32 "
        "{%0,%1,%2,%3}, {%4,%5,%6,%7}, {%8,%9}, {%0,%1,%2,%3};"
        : "+f"(d[0]), "+f"(d[1]), "+f"(d[2]), "+f"(d[3])
        : "r"(a[0]), "r"(a[1]), "r"(a[2]), "r"(a[3]), "r"(b[0]), "r"(b[1]));
}
#define CP_ASYNC16(dst, src) \
    asm volatile("cp.async.cg.shared.global [%0], [%1], 16;" :: "r"(dst), "l"(src) : "memory")
#define CP_COMMIT() asm volatile("cp.async.commit_group;" ::: "memory")
#define CP_WAIT(N)  asm volatile("cp.async.wait_group %0;" :: "n"(N) : "memory")

__device__ __forceinline__ float warp_allsum(float v) {
#pragma unroll
    for (int o = 16; o > 0; o >>= 1) v += __shfl_xor_sync(0xffffffffu, v, o);
    return v;
}

// ===========================================================================
// K1: inv_norms[k] = 1 / ||C[k]||^2   (one warp per code) + fb counter reset
// ===========================================================================
__global__ void vq_norms_kernel(const float* __restrict__ C) {
    int k = blockIdx.x;
    int lane = threadIdx.x;
    if (k == 0 && lane == 0) g_fb_count = 0;
    const float4* row = reinterpret_cast<const float4*>(C + (size_t)k * D_SZ);
    float s = 0.f;
#pragma unroll
    for (int i = 0; i < 2; i++) {
        float4 v = row[lane + 32 * i];
        s += v.x * v.x + v.y * v.y + v.z * v.z + v.w * v.w;
    }
    s = warp_allsum(s);
    if (lane == 0) g_inv_norms[k] = 1.0f / s;
}

// ===========================================================================
// K2: 2-limb bf16 split (a ~= hi + lo, ~17 mantissa bits)
// ===========================================================================
__global__ void vq_split_kernel(const float* __restrict__ src, int n8, int isC) {
    int i = blockIdx.x * blockDim.x + threadIdx.x;
    if (i >= n8) return;
    __nv_bfloat16* dh = isC ? g_Chi : g_Ehi;
    __nv_bfloat16* dl = isC ? g_Clo : g_Elo;
    const float4* p = reinterpret_cast<const float4*>(src) + (size_t)i * 2;
    float4 f0 = p[0], f1 = p[1];
    float v[8] = {f0.x, f0.y, f0.z, f0.w, f1.x, f1.y, f1.z, f1.w};
    union U8 { __nv_bfloat16 h[8]; uint4 u; } uh, ul;
#pragma unroll
    for (int j = 0; j < 8; j++) {
        float a = v[j];
        __nv_bfloat16 bh = __float2bfloat16_rn(a);
        float r = a - __bfloat162float(bh);
        uh.h[j] = bh;
        ul.h[j] = __float2bfloat16_rn(r);
    }
    *reinterpret_cast<uint4*>(dh + (size_t)i * 8) = uh.u;
    *reinterpret_cast<uint4*>(dl + (size_t)i * 8) = ul.u;
}

// ===========================================================================
// K3: 3-term split-bf16 mma.sync GEMM + per-row approx top-2
// grid = 1024: blockIdx = rb*4 + q. CTA: 128 rows x 256 codes, 512 threads.
// A resident in SMEM; B triple-buffered (1 sync per chunk).
// ===========================================================================
__global__ __launch_bounds__(NTHREADS, 1) void vq_gemm_kernel() {
    extern __shared__ char smem[];
    const uint32_t sb = smem_u32(smem);
    const int tid = threadIdx.x;
    const int lane = tid & 31;
    const int wid = tid >> 5;      // 0..15
    const int wm = wid & 3;        // M group: rows wm*32..+32
    const int wn = wid >> 2;       // N group: codes wn*32..+32 (within 128-pass)
    const int rb = blockIdx.x >> 2;
    const int q  = blockIdx.x & 3;
    const int rowA0 = rb * 128;

    float* s_invn = reinterpret_cast<float*>(smem + OFF_INVN);
    float* c_s1 = reinterpret_cast<float*>(smem + OFF_CS1);
    int*   c_i1 = reinterpret_cast<int*>(smem + OFF_CI1);
    float* c_s2 = reinterpret_cast<float*>(smem + OFF_CS2);

    if (tid < 256) s_invn[tid] = g_inv_norms[q * 256 + tid];

    // --- A prologue: load both limbs of this row block, full D (132 KB) ---
#pragma unroll
    for (int j = 0; j < 16; j++) {
        int id = tid + NTHREADS * j;          // 0..8191
        int limb = id >> 12;
        int w = id & 4095;
        int r = w >> 5;                        // 0..127
        int c = w & 31;                        // 16B column
        const __nv_bfloat16* base = limb ? g_Elo : g_Ehi;
        CP_ASYNC16(sb + OFF_A + limb * A_LIMB + r * AT_STRIDE + c * 16,
                   base + (size_t)(rowA0 + r) * D_SZ + c * 8);
    }
    CP_COMMIT();

    // per-thread top-2 state for 4 owned rows (mt*2 + half)
    float st_s1[4], st_s2[4];
    int   st_i1[4];
#pragma unroll
    for (int i = 0; i < 4; i++) { st_s1[i] = -1.f; st_s2[i] = -1.f; st_i1[i] = 0; }

    // B chunk loader: 2 x 16B cp.async per thread
    auto loadB = [&](int buf, int kk, int codeB0) {
#pragma unroll
        for (int j = 0; j < 2; j++) {
            int id = tid + NTHREADS * j;       // 0..1023
            int limb = id >> 9;
            int w = id & 511;
            int r = w >> 2;                    // 0..127
            int c = w & 3;                     // 16B column
            const __nv_bfloat16* base = limb ? g_Clo : g_Chi;
            CP_ASYNC16(sb + OFF_B + buf * BUFB + limb * BT_SZ + r * BT_STRIDE + c * 16,
                       base + (size_t)(codeB0 + r) * D_SZ + kk + c * 8);
        }
        CP_COMMIT();
    };

    const int mi = lane >> 3;
    const int arow_off = ((mi & 1) * 8 + (lane & 7)) * AT_STRIDE;
    const int brow_off = ((mi >> 1) * 8 + (lane & 7)) * BT_STRIDE;

    for (int p = 0; p < 2; p++) {
        const int codeB0 = q * 256 + p * 128;
        float d[2][4][4];
#pragma unroll
        for (int mt = 0; mt < 2; mt++)
#pragma unroll
            for (int nt = 0; nt < 4; nt++)
#pragma unroll
                for (int e = 0; e < 4; e++) d[mt][nt][e] = 0.f;

        loadB(0, 0, codeB0);
        loadB(1, BK, codeB0);
        for (int kc = 0; kc < 8; kc++) {
            const int buf = kc % 3;
            if (kc < 7) { CP_WAIT(1); } else { CP_WAIT(0); }
            __syncthreads();
            if (kc < 6) loadB((kc + 2) % 3, (kc + 2) * BK, codeB0);

#pragma unroll
            for (int ks2 = 0; ks2 < 2; ks2++) {
                const int d0 = kc * BK + ks2 * 16;   // absolute d for A
                const int ksl = ks2 * 16;            // local d within B chunk
                uint32_t afr[2][2][4];
#pragma unroll
                for (int lb = 0; lb < 2; lb++)
#pragma unroll
                    for (int mt = 0; mt < 2; mt++) {
                        uint32_t ad = sb + OFF_A + lb * A_LIMB
                                    + (wm * 32 + mt * 16) * AT_STRIDE + arow_off
                                    + (d0 + (mi >> 1) * 8) * 2;
                        ldsm_x4(afr[lb][mt], ad);
                    }
#pragma unroll
                for (int np = 0; np < 2; np++) {
                    uint32_t bh[4], bl[4];
                    uint32_t bd0 = sb + OFF_B + buf * BUFB
                                 + (wn * 32 + np * 16) * BT_STRIDE + brow_off
                                 + (ksl + (mi & 1) * 8) * 2;
                    ldsm_x4(bh, bd0);
                    ldsm_x4(bl, bd0 + BT_SZ);
#pragma unroll
                    for (int jj = 0; jj < 2; jj++) {
                        int nt = np * 2 + jj;
#pragma unroll
                        for (int mt = 0; mt < 2; mt++) {
                            mma_bf16(d[mt][nt], afr[0][mt], bh + jj * 2);  // hi*hi
                            mma_bf16(d[mt][nt], afr[0][mt], bl + jj * 2);  // hi*lo
                            mma_bf16(d[mt][nt], afr[1][mt], bh + jj * 2);  // lo*hi
                        }
                    }
                }
            }
        }
        __syncthreads();   // protect B buffers before next pass prologue

        // epilogue: fold this pass's 128 codes into per-row top-2
#pragma unroll
        for (int mt = 0; mt < 2; mt++)
#pragma unroll
            for (int nt = 0; nt < 4; nt++) {
                int cb = wn * 32 + nt * 8 + (lane & 3) * 2;   // 0..127
                int cl = p * 128 + cb;
                float in0 = s_invn[cl], in1 = s_invn[cl + 1];
                int gc = q * 256 + cl;
#pragma unroll
                for (int half = 0; half < 2; half++) {
                    int si = mt * 2 + half;
                    float e0 = d[mt][nt][half * 2 + 0];
                    float e1 = d[mt][nt][half * 2 + 1];
                    float sc0 = e0 * e0 * in0;
                    if (sc0 > st_s1[si]) { st_s2[si] = st_s1[si]; st_s1[si] = sc0; st_i1[si] = gc; }
                    else if (sc0 > st_s2[si]) st_s2[si] = sc0;
                    float sc1 = e1 * e1 * in1;
                    if (sc1 > st_s1[si]) { st_s2[si] = st_s1[si]; st_s1[si] = sc1; st_i1[si] = gc + 1; }
                    else if (sc1 > st_s2[si]) st_s2[si] = sc1;
                }
            }
    }

    // cross-thread merge: 16 candidates per row
#pragma unroll
    for (int mt = 0; mt < 2; mt++)
#pragma unroll
        for (int half = 0; half < 2; half++) {
            int r = wm * 32 + mt * 16 + half * 8 + (lane >> 2);
            int slot = wn * 4 + (lane & 3);
            int si = mt * 2 + half;
            c_s1[r * 16 + slot] = st_s1[si];
            c_i1[r * 16 + slot] = st_i1[si];
            c_s2[r * 16 + slot] = st_s2[si];
        }
    __syncthreads();
    if (tid < 128) {
        float S1 = -1.f, S2 = -1.f; int I1 = 0;
#pragma unroll
        for (int s = 0; s < 16; s++) {
            float a1 = c_s1[tid * 16 + s];
            int   ai = c_i1[tid * 16 + s];
            float a2 = c_s2[tid * 16 + s];
            if (a1 > S1) { S2 = (S1 > a2) ? S1 : a2; I1 = ai; S1 = a1; }
            else if (a1 > S2) S2 = a1;
        }
        int o = q * B_SZ + rowA0 + tid;
        g_ts1[o] = S1; g_ti1[o] = I1; g_ts2[o] = S2;
    }
}

// ===========================================================================
// K4: certify winner. Certified rows: exact alpha, write z/idx.
// Uncertified rows: append to fallback list. One warp per row.
// ===========================================================================
__global__ __launch_bounds__(256) void vq_final_kernel(
    const float* __restrict__ E, const float* __restrict__ C,
    float* __restrict__ z_out, float* __restrict__ idx_out, int write_idx)
{
    int warp = threadIdx.x >> 5;
    int lane = threadIdx.x & 31;
    int row = blockIdx.x * 8 + warp;
    const float4* E4 = reinterpret_cast<const float4*>(E);
    const float4* C4 = reinterpret_cast<const float4*>(C);

    float4 ev0 = E4[(size_t)row * 64 + lane * 2];
    float4 ev1 = E4[(size_t)row * 64 + lane * 2 + 1];
    float en2 = warp_allsum(ev0.x * ev0.x + ev0.y * ev0.y + ev0.z * ev0.z + ev0.w * ev0.w +
                            ev1.x * ev1.x + ev1.y * ev1.y + ev1.z * ev1.z + ev1.w * ev1.w);

    // merge 4 quarter top-2 triples
    float S1 = -1.f, S2 = -1.f; int I1 = 0;
#pragma unroll
    for (int qq = 0; qq < 4; qq++) {
        float a1 = g_ts1[qq * B_SZ + row];
        int   ai = g_ti1[qq * B_SZ + row];
        float a2 = g_ts2[qq * B_SZ + row];
        if (a1 > S1) { S2 = (S1 > a2) ? S1 : a2; I1 = ai; S1 = a1; }
        else if (a1 > S2) S2 = a1;
    }

    float eps = en2 * (1.0f / 8192.0f);   // 2^-13 * ||e||^2 (proven threshold)
    if (S1 - S2 > eps) {
        // certified: exact dot for winner -> alpha, z
        float4 cv0 = __ldg(&C4[(size_t)I1 * 64 + lane * 2]);
        float4 cv1 = __ldg(&C4[(size_t)I1 * 64 + lane * 2 + 1]);
        float pp = ev0.x * cv0.x + ev0.y * cv0.y + ev0.z * cv0.z + ev0.w * cv0.w +
                   ev1.x * cv1.x + ev1.y * cv1.y + ev1.z * cv1.z + ev1.w * cv1.w;
        float dot = warp_allsum(pp);
        float alpha = dot * g_inv_norms[I1];
        float4* Z4 = reinterpret_cast<float4*>(z_out);
        Z4[(size_t)row * 64 + lane * 2] =
            make_float4(alpha * cv0.x, alpha * cv0.y, alpha * cv0.z, alpha * cv0.w);
        Z4[(size_t)row * 64 + lane * 2 + 1] =
            make_float4(alpha * cv1.x, alpha * cv1.y, alpha * cv1.z, alpha * cv1.w);
        if (lane == 0 && write_idx) idx_out[row] = (float)I1;
    } else {
        if (lane == 0) {
            int pos = atomicAdd(&g_fb_count, 1);
            g_fb_rows[pos] = row;
        }
    }
}

// ===========================================================================
// K5: exact fp32 rescan for fallback rows. One CTA per row (grid-stride).
// Warp w scans codes [128w, 128w+128), 4 codes per iteration (4 independent
// shuffle chains), coalesced codebook loads.
// ===========================================================================
__global__ __launch_bounds__(256) void vq_fb_kernel(
    const float* __restrict__ E, const float* __restrict__ C,
    float* __restrict__ z_out, float* __restrict__ idx_out, int write_idx)
{
    __shared__ float se[256];
    __shared__ float ws[8];
    __shared__ int   wi[8];
    __shared__ float s_alpha;
    __shared__ int   s_k;
    const int tid = threadIdx.x;
    const int warp = tid >> 5;
    const int lane = tid & 31;
    const float4* C4 = reinterpret_cast<const float4*>(C);

    const int nfb = g_fb_count;
    for (int it = blockIdx.x; it < nfb; it += FB_CTAS) {
        const int row = g_fb_rows[it];
        se[tid] = E[(size_t)row * D_SZ + tid];
        __syncthreads();
        const float4 ea = *reinterpret_cast<const float4*>(&se[lane * 8]);
        const float4 eb = *reinterpret_cast<const float4*>(&se[lane * 8 + 4]);

        float best = -1.f; int bi = 0;
        for (int kk = 0; kk < 128; kk += 4) {
            float dots[4];
#pragma unroll
            for (int u = 0; u < 4; u++) {
                int k = warp * 128 + kk + u;
                float4 c0 = __ldg(&C4[(size_t)k * 64 + lane * 2]);
                float4 c1 = __ldg(&C4[(size_t)k * 64 + lane * 2 + 1]);
                dots[u] = ea.x * c0.x + ea.y * c0.y + ea.z * c0.z + ea.w * c0.w +
                          eb.x * c1.x + eb.y * c1.y + eb.z * c1.z + eb.w * c1.w;
            }
#pragma unroll
            for (int o = 16; o > 0; o >>= 1)
#pragma unroll
                for (int u = 0; u < 4; u++)
                    dots[u] += __shfl_xor_sync(0xffffffffu, dots[u], o);
#pragma unroll
            for (int u = 0; u < 4; u++) {
                int k = warp * 128 + kk + u;
                float sc = dots[u] * dots[u] * g_inv_norms[k];
                if (sc > best) { best = sc; bi = k; }   // ascending k: first min kept
            }
        }
        if (lane == 0) { ws[warp] = best; wi[warp] = bi; }
        __syncthreads();
        if (tid == 0) {
            float bb = -1.f; int bk = 0;
#pragma unroll
            for (int w = 0; w < 8; w++)
                if (ws[w] > bb) { bb = ws[w]; bk = wi[w]; }   // ascending w: lowest idx
            s_k = bk;
        }
        __syncthreads();
        const int kb = s_k;
        if (warp == 0) {
            float4 c0 = __ldg(&C4[(size_t)kb * 64 + lane * 2]);
            float4 c1 = __ldg(&C4[(size_t)kb * 64 + lane * 2 + 1]);
            float pp = ea.x * c0.x + ea.y * c0.y + ea.z * c0.z + ea.w * c0.w +
                       eb.x * c1.x + eb.y * c1.y + eb.z * c1.z + eb.w * c1.w;
            float dot = warp_allsum(pp);
            if (lane == 0) {
                s_alpha = dot * g_inv_norms[kb];
                if (write_idx) idx_out[row] = (float)kb;
            }
        }
        __syncthreads();
        z_out[(size_t)row * D_SZ + tid] = s_alpha * C[(size_t)kb * D_SZ + tid];
        __syncthreads();   // protect se / s_alpha before next iteration
    }
}

// ===========================================================================
extern "C" void kernel_launch(void* const* d_in, const int* in_sizes, int n_in,
                              void* d_out, int out_size) {
    const float* E = (const float*)d_in[0];
    const float* C = (const float*)d_in[1];
    float* z = (float*)d_out;
    float* idx = z + (size_t)B_SZ * D_SZ;
    int write_idx = (out_size >= B_SZ * D_SZ + B_SZ) ? 1 : 0;

    cudaFuncSetAttribute(vq_gemm_kernel,
                         cudaFuncAttributeMaxDynamicSharedMemorySize, SMEM_K3);

    vq_norms_kernel<<<K_SZ, 32>>>(C);
    vq_split_kernel<<<(B_SZ * D_SZ / 8 + 255) / 256, 256>>>(E, B_SZ * D_SZ / 8, 0);
    vq_split_kernel<<<(K_SZ * D_SZ / 8 + 255) / 256, 256>>>(C, K_SZ * D_SZ / 8, 1);
    vq_gemm_kernel<<<1024, NTHREADS, SMEM_K3>>>();
    vq_final_kernel<<<B_SZ / 8, 256>>>(E, C, z, idx, write_idx);
    vq_fb_kernel<<<FB_CTAS, 256>>>(E, C, z, idx, write_idx);
}

// round 13
// speedup vs baseline: 1.8770x; 1.0393x over previous
#include <cuda_runtime.h>
#include <cuda_bf16.h>
#include <cstdint>

// ===========================================================================
// Problem constants
// ===========================================================================
#define B_SZ 32768
#define D_SZ 256
#define K_SZ 1024

#define NTHREADS 512       // 16 warps
#define BK 64              // d-chunk per B pipeline stage (double-buffered)
#define FB_CTAS 256        // fallback kernel grid

// --- SMEM layout (bytes) for K3 ---
// B tiles: [buf(2)][limb(2)] each 128 codes x 64 d bf16, row stride 144B
#define BT_STRIDE 144
#define BT_SZ     18432          // 128*144
#define BUFB      36864          // 2 limbs
#define OFF_B     0              // 2 bufs -> 73728
// A tiles: [limb(2)] 128 rows x 256 d bf16, row stride 528B (512 + 16 pad)
#define AT_STRIDE 528
#define A_LIMB    67584          // 128*528
#define OFF_A     73728          // 2 limbs -> ends 208896
#define OFF_INVN  208896         // 256 floats -> 209920
#define SMEM_K3   209920
// merge arrays overlay the B region (only used after all MMA reads + sync)
#define OFF_CS1   0              // float [128][16] -> 8192
#define OFF_CI1   8192           // int   [128][16] -> 16384
#define OFF_CS2   16384          // float [128][16] -> 24576

// ===========================================================================
// Device scratch (allocation-free rule: __device__ globals)
// ===========================================================================
__device__ float g_inv_norms[K_SZ];
__device__ __align__(16) __nv_bfloat16 g_Ehi[B_SZ * D_SZ];
__device__ __align__(16) __nv_bfloat16 g_Elo[B_SZ * D_SZ];
__device__ __align__(16) __nv_bfloat16 g_Chi[K_SZ * D_SZ];
__device__ __align__(16) __nv_bfloat16 g_Clo[K_SZ * D_SZ];
// per (quarter, row) top-2 approx results
__device__ float g_ts1[4 * B_SZ];
__device__ int   g_ti1[4 * B_SZ];
__device__ float g_ts2[4 * B_SZ];
// fallback compaction
__device__ int g_fb_count;
__device__ int g_fb_rows[B_SZ];

// ===========================================================================
// PTX helpers (plain sm_103-safe: mma.sync / ldmatrix / cp.async only)
// ===========================================================================
__device__ __forceinline__ uint32_t smem_u32(const void* p) {
    uint32_t a;
    asm("{ .reg .u64 t; cvta.to.shared.u64 t, %1; cvt.u32.u64 %0, t; }" : "=r"(a) : "l"(p));
    return a;
}
__device__ __forceinline__ void ldsm_x4(uint32_t r[4], uint32_t addr) {
    asm volatile("ldmatrix.sync.aligned.m8n8.x4.shared.b16 {%0,%1,%2,%3}, [%4];"
                 : "=r"(r[0]), "=r"(r[1]), "=r"(r[2]), "=r"(r[3]) : "r"(addr));
}
__device__ __forceinline__ void mma_bf16(float d[4], const uint32_t a[4], const uint32_t* b) {
    asm volatile(
        "mma.sync.aligned.m16n8k16.row.col.f32.bf16.bf16.f32 "
        "{%0,%1,%2,%3}, {%4,%5,%6,%7}, {%8,%9}, {%0,%1,%2,%3};"
        : "+f"(d[0]), "+f"(d[1]), "+f"(d[2]), "+f"(d[3])
        : "r"(a[0]), "r"(a[1]), "r"(a[2]), "r"(a[3]), "r"(b[0]), "r"(b[1]));
}
#define CP_ASYNC16(dst, src) \
    asm volatile("cp.async.cg.shared.global [%0], [%1], 16;" :: "r"(dst), "l"(src) : "memory")
#define CP_COMMIT() asm volatile("cp.async.commit_group;" ::: "memory")
#define CP_WAIT(N)  asm volatile("cp.async.wait_group %0;" :: "n"(N) : "memory")

__device__ __forceinline__ float warp_allsum(float v) {
#pragma unroll
    for (int o = 16; o > 0; o >>= 1) v += __shfl_xor_sync(0xffffffffu, v, o);
    return v;
}

// ===========================================================================
// K1: inv_norms[k] = 1 / ||C[k]||^2   (one warp per code) + fb counter reset
// ===========================================================================
__global__ void vq_norms_kernel(const float* __restrict__ C) {
    int k = blockIdx.x;
    int lane = threadIdx.x;
    if (k == 0 && lane == 0) g_fb_count = 0;
    const float4* row = reinterpret_cast<const float4*>(C + (size_t)k * D_SZ);
    float s = 0.f;
#pragma unroll
    for (int i = 0; i < 2; i++) {
        float4 v = row[lane + 32 * i];
        s += v.x * v.x + v.y * v.y + v.z * v.z + v.w * v.w;
    }
    s = warp_allsum(s);
    if (lane == 0) g_inv_norms[k] = 1.0f / s;
}

// ===========================================================================
// K2: 2-limb bf16 split (a ~= hi + lo, ~17 mantissa bits)
// ===========================================================================
__global__ void vq_split_kernel(const float* __restrict__ src, int n8, int isC) {
    int i = blockIdx.x * blockDim.x + threadIdx.x;
    if (i >= n8) return;
    __nv_bfloat16* dh = isC ? g_Chi : g_Ehi;
    __nv_bfloat16* dl = isC ? g_Clo : g_Elo;
    const float4* p = reinterpret_cast<const float4*>(src) + (size_t)i * 2;
    float4 f0 = p[0], f1 = p[1];
    float v[8] = {f0.x, f0.y, f0.z, f0.w, f1.x, f1.y, f1.z, f1.w};
    union U8 { __nv_bfloat16 h[8]; uint4 u; } uh, ul;
#pragma unroll
    for (int j = 0; j < 8; j++) {
        float a = v[j];
        __nv_bfloat16 bh = __float2bfloat16_rn(a);
        float r = a - __bfloat162float(bh);
        uh.h[j] = bh;
        ul.h[j] = __float2bfloat16_rn(r);
    }
    *reinterpret_cast<uint4*>(dh + (size_t)i * 8) = uh.u;
    *reinterpret_cast<uint4*>(dl + (size_t)i * 8) = ul.u;
}

// ===========================================================================
// K3: 3-term split-bf16 mma.sync GEMM + per-row approx top-2
// grid = 1024: blockIdx = rb*4 + q. CTA: 128 rows x 256 codes, 512 threads.
// A resident in SMEM; B double-buffered in BK=64 chunks (4 syncs/pass).
// ===========================================================================
__global__ __launch_bounds__(NTHREADS, 1) void vq_gemm_kernel() {
    extern __shared__ char smem[];
    const uint32_t sb = smem_u32(smem);
    const int tid = threadIdx.x;
    const int lane = tid & 31;
    const int wid = tid >> 5;      // 0..15
    const int wm = wid & 3;        // M group: rows wm*32..+32
    const int wn = wid >> 2;       // N group: codes wn*32..+32 (within 128-pass)
    const int rb = blockIdx.x >> 2;
    const int q  = blockIdx.x & 3;
    const int rowA0 = rb * 128;

    float* s_invn = reinterpret_cast<float*>(smem + OFF_INVN);

    if (tid < 256) s_invn[tid] = g_inv_norms[q * 256 + tid];

    // --- A prologue: load both limbs of this row block, full D (132 KB) ---
#pragma unroll
    for (int j = 0; j < 16; j++) {
        int id = tid + NTHREADS * j;          // 0..8191
        int limb = id >> 12;
        int w = id & 4095;
        int r = w >> 5;                        // 0..127
        int c = w & 31;                        // 16B column
        const __nv_bfloat16* base = limb ? g_Elo : g_Ehi;
        CP_ASYNC16(sb + OFF_A + limb * A_LIMB + r * AT_STRIDE + c * 16,
                   base + (size_t)(rowA0 + r) * D_SZ + c * 8);
    }
    CP_COMMIT();

    // per-thread top-2 state for 4 owned rows (mt*2 + half)
    float st_s1[4], st_s2[4];
    int   st_i1[4];
#pragma unroll
    for (int i = 0; i < 4; i++) { st_s1[i] = -1.f; st_s2[i] = -1.f; st_i1[i] = 0; }

    // B chunk loader: 128 codes x 64 bf16 x 2 limbs = 32 KB -> 4 x 16B / thread
    auto loadB = [&](int buf, int kk, int codeB0) {
#pragma unroll
        for (int j = 0; j < 4; j++) {
            int id = tid + NTHREADS * j;       // 0..2047
            int limb = id >> 10;
            int w = id & 1023;
            int r = w >> 3;                    // 0..127
            int c = w & 7;                     // 16B column (8 per 128B row)
            const __nv_bfloat16* base = limb ? g_Clo : g_Chi;
            CP_ASYNC16(sb + OFF_B + buf * BUFB + limb * BT_SZ + r * BT_STRIDE + c * 16,
                       base + (size_t)(codeB0 + r) * D_SZ + kk + c * 8);
        }
        CP_COMMIT();
    };

    const int mi = lane >> 3;
    const int arow_off = ((mi & 1) * 8 + (lane & 7)) * AT_STRIDE;
    const int brow_off = ((mi >> 1) * 8 + (lane & 7)) * BT_STRIDE;

    for (int p = 0; p < 2; p++) {
        const int codeB0 = q * 256 + p * 128;
        float d[2][4][4];
#pragma unroll
        for (int mt = 0; mt < 2; mt++)
#pragma unroll
            for (int nt = 0; nt < 4; nt++)
#pragma unroll
                for (int e = 0; e < 4; e++) d[mt][nt][e] = 0.f;

        loadB(0, 0, codeB0);
        for (int kc = 0; kc < 4; kc++) {
            CP_WAIT(0);
            __syncthreads();
            if (kc < 3) loadB((kc + 1) & 1, (kc + 1) * BK, codeB0);
            const int buf = kc & 1;

#pragma unroll
            for (int ks2 = 0; ks2 < 4; ks2++) {
                const int d0 = kc * BK + ks2 * 16;   // absolute d for A
                const int ksl = ks2 * 16;            // local d within B chunk
                uint32_t afr[2][2][4];
#pragma unroll
                for (int lb = 0; lb < 2; lb++)
#pragma unroll
                    for (int mt = 0; mt < 2; mt++) {
                        uint32_t ad = sb + OFF_A + lb * A_LIMB
                                    + (wm * 32 + mt * 16) * AT_STRIDE + arow_off
                                    + (d0 + (mi >> 1) * 8) * 2;
                        ldsm_x4(afr[lb][mt], ad);
                    }
#pragma unroll
                for (int np = 0; np < 2; np++) {
                    uint32_t bh[4], bl[4];
                    uint32_t bd0 = sb + OFF_B + buf * BUFB
                                 + (wn * 32 + np * 16) * BT_STRIDE + brow_off
                                 + (ksl + (mi & 1) * 8) * 2;
                    ldsm_x4(bh, bd0);
                    ldsm_x4(bl, bd0 + BT_SZ);
#pragma unroll
                    for (int jj = 0; jj < 2; jj++) {
                        int nt = np * 2 + jj;
#pragma unroll
                        for (int mt = 0; mt < 2; mt++) {
                            mma_bf16(d[mt][nt], afr[0][mt], bh + jj * 2);  // hi*hi
                            mma_bf16(d[mt][nt], afr[0][mt], bl + jj * 2);  // hi*lo
                            mma_bf16(d[mt][nt], afr[1][mt], bh + jj * 2);  // lo*hi
                        }
                    }
                }
            }
        }

        // epilogue (registers + invn smem only): fold 128 codes into top-2
#pragma unroll
        for (int mt = 0; mt < 2; mt++)
#pragma unroll
            for (int nt = 0; nt < 4; nt++) {
                int cb = wn * 32 + nt * 8 + (lane & 3) * 2;   // 0..127
                int cl = p * 128 + cb;
                float in0 = s_invn[cl], in1 = s_invn[cl + 1];
                int gc = q * 256 + cl;
#pragma unroll
                for (int half = 0; half < 2; half++) {
                    int si = mt * 2 + half;
                    float e0 = d[mt][nt][half * 2 + 0];
                    float e1 = d[mt][nt][half * 2 + 1];
                    float sc0 = e0 * e0 * in0;
                    if (sc0 > st_s1[si]) { st_s2[si] = st_s1[si]; st_s1[si] = sc0; st_i1[si] = gc; }
                    else if (sc0 > st_s2[si]) st_s2[si] = sc0;
                    float sc1 = e1 * e1 * in1;
                    if (sc1 > st_s1[si]) { st_s2[si] = st_s1[si]; st_s1[si] = sc1; st_i1[si] = gc + 1; }
                    else if (sc1 > st_s2[si]) st_s2[si] = sc1;
                }
            }
    }

    // ensure all B reads done before overlaying merge arrays on the B region
    __syncthreads();
    float* c_s1 = reinterpret_cast<float*>(smem + OFF_CS1);
    int*   c_i1 = reinterpret_cast<int*>(smem + OFF_CI1);
    float* c_s2 = reinterpret_cast<float*>(smem + OFF_CS2);

    // cross-thread merge: 16 candidates per row
#pragma unroll
    for (int mt = 0; mt < 2; mt++)
#pragma unroll
        for (int half = 0; half < 2; half++) {
            int r = wm * 32 + mt * 16 + half * 8 + (lane >> 2);
            int slot = wn * 4 + (lane & 3);
            int si = mt * 2 + half;
            c_s1[r * 16 + slot] = st_s1[si];
            c_i1[r * 16 + slot] = st_i1[si];
            c_s2[r * 16 + slot] = st_s2[si];
        }
    __syncthreads();
    if (tid < 128) {
        float S1 = -1.f, S2 = -1.f; int I1 = 0;
#pragma unroll
        for (int s = 0; s < 16; s++) {
            float a1 = c_s1[tid * 16 + s];
            int   ai = c_i1[tid * 16 + s];
            float a2 = c_s2[tid * 16 + s];
            if (a1 > S1) { S2 = (S1 > a2) ? S1 : a2; I1 = ai; S1 = a1; }
            else if (a1 > S2) S2 = a1;
        }
        int o = q * B_SZ + rowA0 + tid;
        g_ts1[o] = S1; g_ti1[o] = I1; g_ts2[o] = S2;
    }
}

// ===========================================================================
// K4: certify winner. Certified rows: exact alpha, write z/idx.
// Uncertified rows: append to fallback list. One warp per row.
// ===========================================================================
__global__ __launch_bounds__(256) void vq_final_kernel(
    const float* __restrict__ E, const float* __restrict__ C,
    float* __restrict__ z_out, float* __restrict__ idx_out, int write_idx)
{
    int warp = threadIdx.x >> 5;
    int lane = threadIdx.x & 31;
    int row = blockIdx.x * 8 + warp;
    const float4* E4 = reinterpret_cast<const float4*>(E);
    const float4* C4 = reinterpret_cast<const float4*>(C);

    float4 ev0 = E4[(size_t)row * 64 + lane * 2];
    float4 ev1 = E4[(size_t)row * 64 + lane * 2 + 1];
    float en2 = warp_allsum(ev0.x * ev0.x + ev0.y * ev0.y + ev0.z * ev0.z + ev0.w * ev0.w +
                            ev1.x * ev1.x + ev1.y * ev1.y + ev1.z * ev1.z + ev1.w * ev1.w);

    // merge 4 quarter top-2 triples
    float S1 = -1.f, S2 = -1.f; int I1 = 0;
#pragma unroll
    for (int qq = 0; qq < 4; qq++) {
        float a1 = g_ts1[qq * B_SZ + row];
        int   ai = g_ti1[qq * B_SZ + row];
        float a2 = g_ts2[qq * B_SZ + row];
        if (a1 > S1) { S2 = (S1 > a2) ? S1 : a2; I1 = ai; S1 = a1; }
        else if (a1 > S2) S2 = a1;
    }

    float eps = en2 * (1.0f / 8192.0f);   // 2^-13 * ||e||^2 (proven threshold)
    if (S1 - S2 > eps) {
        float4 cv0 = __ldg(&C4[(size_t)I1 * 64 + lane * 2]);
        float4 cv1 = __ldg(&C4[(size_t)I1 * 64 + lane * 2 + 1]);
        float pp = ev0.x * cv0.x + ev0.y * cv0.y + ev0.z * cv0.z + ev0.w * cv0.w +
                   ev1.x * cv1.x + ev1.y * cv1.y + ev1.z * cv1.z + ev1.w * cv1.w;
        float dot = warp_allsum(pp);
        float alpha = dot * g_inv_norms[I1];
        float4* Z4 = reinterpret_cast<float4*>(z_out);
        Z4[(size_t)row * 64 + lane * 2] =
            make_float4(alpha * cv0.x, alpha * cv0.y, alpha * cv0.z, alpha * cv0.w);
        Z4[(size_t)row * 64 + lane * 2 + 1] =
            make_float4(alpha * cv1.x, alpha * cv1.y, alpha * cv1.z, alpha * cv1.w);
        if (lane == 0 && write_idx) idx_out[row] = (float)I1;
    } else {
        if (lane == 0) {
            int pos = atomicAdd(&g_fb_count, 1);
            g_fb_rows[pos] = row;
        }
    }
}

// ===========================================================================
// K5: exact fp32 rescan for fallback rows. 8 rows per CTA (grid-stride):
// all 8 e-rows lane-distributed in registers; warp w scans contiguous codes
// [128w, 128w+128) once -> codebook traffic / 8. 8 independent shuffle chains.
// ===========================================================================
__global__ __launch_bounds__(256) void vq_fb_kernel(
    const float* __restrict__ E, const float* __restrict__ C,
    float* __restrict__ z_out, float* __restrict__ idx_out, int write_idx)
{
    __shared__ float se[8][256];
    __shared__ float ws[8][8];   // [row][warp]
    __shared__ int   wi[8][8];
    __shared__ int   s_rid[8];
    __shared__ int   s_kb[8];
    const int tid = threadIdx.x;
    const int warp = tid >> 5;
    const int lane = tid & 31;
    const float4* C4 = reinterpret_cast<const float4*>(C);

    const int nfb = g_fb_count;
    const int ngrp = (nfb + 7) >> 3;
    for (int g = blockIdx.x; g < ngrp; g += FB_CTAS) {
        const int r0 = g * 8;
        const int cnt = (nfb - r0 < 8) ? (nfb - r0) : 8;
        if (tid < 8) s_rid[tid] = (tid < cnt) ? g_fb_rows[r0 + tid] : -1;
        __syncthreads();
#pragma unroll
        for (int rr = 0; rr < 8; rr++)
            se[rr][tid] = (s_rid[rr] >= 0) ? E[(size_t)s_rid[rr] * D_SZ + tid] : 0.f;
        __syncthreads();

        // stage all 8 rows into registers (lane owns dims [lane*8, lane*8+8))
        float4 ea[8], eb[8];
#pragma unroll
        for (int r = 0; r < 8; r++) {
            ea[r] = *reinterpret_cast<const float4*>(&se[r][lane * 8]);
            eb[r] = *reinterpret_cast<const float4*>(&se[r][lane * 8 + 4]);
        }

        float best[8]; int bi[8];
#pragma unroll
        for (int r = 0; r < 8; r++) { best[r] = -1.f; bi[r] = 0; }

        const int k0 = warp * 128;
        for (int kk = 0; kk < 128; kk++) {
            const int k = k0 + kk;
            float4 c0 = __ldg(&C4[(size_t)k * 64 + lane * 2]);
            float4 c1 = __ldg(&C4[(size_t)k * 64 + lane * 2 + 1]);
            float pp[8];
#pragma unroll
            for (int r = 0; r < 8; r++)
                pp[r] = ea[r].x * c0.x + ea[r].y * c0.y + ea[r].z * c0.z + ea[r].w * c0.w +
                        eb[r].x * c1.x + eb[r].y * c1.y + eb[r].z * c1.z + eb[r].w * c1.w;
#pragma unroll
            for (int o = 16; o > 0; o >>= 1)
#pragma unroll
                for (int r = 0; r < 8; r++)
                    pp[r] += __shfl_xor_sync(0xffffffffu, pp[r], o);
            const float invn = g_inv_norms[k];
#pragma unroll
            for (int r = 0; r < 8; r++) {
                float sc = pp[r] * pp[r] * invn;
                if (sc > best[r]) { best[r] = sc; bi[r] = k; }  // ascending k
            }
        }
        if (lane == 0) {
#pragma unroll
            for (int r = 0; r < 8; r++) { ws[r][warp] = best[r]; wi[r][warp] = bi[r]; }
        }
        __syncthreads();
        if (tid < 8) {   // merge row tid across warps (ascending warp = ascending k block)
            float bb = -1.f; int bk = 0;
#pragma unroll
            for (int w = 0; w < 8; w++)
                if (ws[tid][w] > bb) { bb = ws[tid][w]; bk = wi[tid][w]; }
            s_kb[tid] = bk;
        }
        __syncthreads();

        // warp r finalizes row r: exact dot -> alpha -> z, idx
        const int row = s_rid[warp];
        if (row >= 0) {
            const int kb = s_kb[warp];
            float4 c0 = __ldg(&C4[(size_t)kb * 64 + lane * 2]);
            float4 c1 = __ldg(&C4[(size_t)kb * 64 + lane * 2 + 1]);
            float pp = ea[warp].x * c0.x + ea[warp].y * c0.y + ea[warp].z * c0.z + ea[warp].w * c0.w +
                       eb[warp].x * c1.x + eb[warp].y * c1.y + eb[warp].z * c1.z + eb[warp].w * c1.w;
            float dot = warp_allsum(pp);
            float alpha = dot * g_inv_norms[kb];
            float4* Z4 = reinterpret_cast<float4*>(z_out);
            Z4[(size_t)row * 64 + lane * 2] =
                make_float4(alpha * c0.x, alpha * c0.y, alpha * c0.z, alpha * c0.w);
            Z4[(size_t)row * 64 + lane * 2 + 1] =
                make_float4(alpha * c1.x, alpha * c1.y, alpha * c1.z, alpha * c1.w);
            if (lane == 0 && write_idx) idx_out[row] = (float)kb;
        }
        __syncthreads();
    }
}

// ===========================================================================
extern "C" void kernel_launch(void* const* d_in, const int* in_sizes, int n_in,
                              void* d_out, int out_size) {
    const float* E = (const float*)d_in[0];
    const float* C = (const float*)d_in[1];
    float* z = (float*)d_out;
    float* idx = z + (size_t)B_SZ * D_SZ;
    int write_idx = (out_size >= B_SZ * D_SZ + B_SZ) ? 1 : 0;

    cudaFuncSetAttribute(vq_gemm_kernel,
                         cudaFuncAttributeMaxDynamicSharedMemorySize, SMEM_K3);

    vq_norms_kernel<<<K_SZ, 32>>>(C);
    vq_split_kernel<<<(B_SZ * D_SZ / 8 + 255) / 256, 256>>>(E, B_SZ * D_SZ / 8, 0);
    vq_split_kernel<<<(K_SZ * D_SZ / 8 + 255) / 256, 256>>>(C, K_SZ * D_SZ / 8, 1);
    vq_gemm_kernel<<<1024, NTHREADS, SMEM_K3>>>();
    vq_final_kernel<<<B_SZ / 8, 256>>>(E, C, z, idx, write_idx);
    vq_fb_kernel<<<FB_CTAS, 256>>>(E, C, z, idx, write_idx);
}